// round 2
// baseline (speedup 1.0000x reference)
#include <cuda_runtime.h>
#include <cstddef>

#define NN 50000
#define NE 800000

// ---------------- scratch (device globals; no allocation allowed) ----------
__device__ int   g_is64;               // 1 if edge_index is int64, 0 if int32
__device__ float g_deg[NN];            // degree -> overwritten with d^{-1/2}
__device__ int   g_cnt[NN];
__device__ int   g_cur[NN];
__device__ int   g_rowptr[NN + 1];
__device__ int   g_esrc[NE];
__device__ float g_enorm[NE];
__device__ float g_bufA[(size_t)NN * 512];   // h1 / h2
__device__ float g_bufB[(size_t)NN * 256];   // a1 / t2 / t3

// ---------------- dtype detection ----------------
// int64 little-endian with values < 2^31: every odd 32-bit word == 0.
// int32 index array: odd words are random node ids -> some nonzero.
__global__ void detect_dtype(const unsigned int* __restrict__ w) {
    int tid = blockIdx.x * blockDim.x + threadIdx.x;
    if (tid == 0) g_is64 = 1;   // racy-but-ordered OK: grid writes 0 only
    for (int k = tid; k < NE; k += gridDim.x * blockDim.x) {
        if (w[2 * k + 1] != 0u) { g_is64 = 0; break; }
    }
}

__device__ __forceinline__ int load_idx(const void* ei, long long pos) {
    if (g_is64) return (int)((const long long*)ei)[pos];
    return ((const int*)ei)[pos];
}

// ---------------- preprocessing ----------------
__global__ void init_node(float* deg, int* cnt, int* cur) {
    int i = blockIdx.x * blockDim.x + threadIdx.x;
    if (i < NN) { deg[i] = 1.0f; cnt[i] = 0; cur[i] = 0; }   // self-loop weight 1
}

__global__ void edge_deg_count(const void* __restrict__ ei,
                               const float* __restrict__ w,
                               float* deg, int* cnt) {
    int e = blockIdx.x * blockDim.x + threadIdx.x;
    if (e >= NE) return;
    int d = load_idx(ei, (long long)NE + e);
    if ((unsigned)d >= NN) return;      // defensive
    atomicAdd(&deg[d], w[e]);
    atomicAdd(&cnt[d], 1);
}

__global__ void make_dinv(float* deg) {
    int i = blockIdx.x * blockDim.x + threadIdx.x;
    if (i < NN) deg[i] = rsqrtf(deg[i]);   // deg >= 1 always (self-loop)
}

// one-block exclusive scan of 50k counts
__global__ void scan_rowptr(const int* __restrict__ cnt, int* __restrict__ rowptr) {
    __shared__ int sh[1024];
    const int n = NN;
    int t = threadIdx.x;
    int chunk = (n + 1023) >> 10;
    int b = t * chunk;
    int e = b + chunk; if (e > n) e = n;
    if (b > n) b = n;
    int sum = 0;
    for (int i = b; i < e; i++) sum += cnt[i];
    sh[t] = sum;
    __syncthreads();
    for (int off = 1; off < 1024; off <<= 1) {
        int v = (t >= off) ? sh[t - off] : 0;
        __syncthreads();
        sh[t] += v;
        __syncthreads();
    }
    int run = (t == 0) ? 0 : sh[t - 1];
    for (int i = b; i < e; i++) { rowptr[i] = run; run += cnt[i]; }
    if (t == 1023) rowptr[n] = sh[1023];
}

__global__ void edge_fill(const void* __restrict__ ei,
                          const float* __restrict__ w,
                          const float* __restrict__ dinv,
                          const int* __restrict__ rowptr,
                          int* cur, int* esrc, float* enorm) {
    int e = blockIdx.x * blockDim.x + threadIdx.x;
    if (e >= NE) return;
    int s = load_idx(ei, e);
    int d = load_idx(ei, (long long)NE + e);
    if ((unsigned)s >= NN || (unsigned)d >= NN) return;   // defensive
    float nm = dinv[s] * w[e] * dinv[d];
    int pos = rowptr[d] + atomicAdd(&cur[d], 1);
    esrc[pos] = s;
    enorm[pos] = nm;
}

// ---------------- CSR gather-reduce aggregation ----------------
// out[i,d] = (opt bias[d]) + dinv[i]^2 * H[i,d] + sum_j norm_j * H[src_j,d]
// blockDim.x == D (128 or 256); one block per node; fully coalesced writes.
__global__ void agg_csr(const float* __restrict__ H, float* __restrict__ out,
                        const int* __restrict__ rowptr, const int* __restrict__ esrc,
                        const float* __restrict__ enorm, const float* __restrict__ dinv,
                        const float* __restrict__ bias, int D, int doRelu) {
    int i = blockIdx.x;
    int d = threadIdx.x;
    float di = dinv[i];
    float acc = di * di * H[(size_t)i * D + d];
    if (bias) acc += bias[d];
    int jb = rowptr[i], je = rowptr[i + 1];
    float acc2 = 0.f;
    int j = jb;
    for (; j + 1 < je; j += 2) {
        int s0 = esrc[j], s1 = esrc[j + 1];
        float n0 = enorm[j], n1 = enorm[j + 1];
        acc  += n0 * H[(size_t)s0 * D + d];
        acc2 += n1 * H[(size_t)s1 * D + d];
    }
    if (j < je) acc += enorm[j] * H[(size_t)esrc[j] * D + d];
    acc += acc2;
    if (doRelu) acc = fmaxf(acc, 0.f);
    out[(size_t)i * D + d] = acc;
}

// ---------------- fp32 SIMT GEMM: C[M,N] = A[M,K] @ B[K,N] (+bias, relu) ----
#define BM 128
#define BN 128
#define BK 8
#define TM 8
#define TN 8

__global__ __launch_bounds__(256, 2)
void sgemm(const float* __restrict__ A, const float* __restrict__ B,
           const float* __restrict__ bias, float* __restrict__ C,
           int M, int N, int K, int doRelu) {
    __shared__ float As[BK][BM];
    __shared__ float Bs[BK][BN];

    int bx = blockIdx.x;       // N tile
    int by = blockIdx.y;       // M tile
    int tid = threadIdx.x;     // 256 threads
    int tx = tid & 15;         // 16 x 16 thread grid, 8x8 micro-tiles
    int ty = tid >> 4;

    // A-tile load mapping: 128 rows x 8 cols = 256 float4 (one per thread)
    int aRow = tid >> 1;
    int aCol = (tid & 1) * 4;
    // B-tile load mapping: 8 rows x 128 cols = 256 float4
    int bRow = tid >> 5;
    int bCol = (tid & 31) * 4;

    int aGRow = by * BM + aRow;
    int cColBase = bx * BN + tx * TN;

    float acc[TM][TN];
#pragma unroll
    for (int i = 0; i < TM; i++)
#pragma unroll
        for (int jj = 0; jj < TN; jj++) acc[i][jj] = 0.f;

    for (int k0 = 0; k0 < K; k0 += BK) {
        float4 a4;
        if (aGRow < M) a4 = *(const float4*)(A + (size_t)aGRow * K + k0 + aCol);
        else           a4 = make_float4(0.f, 0.f, 0.f, 0.f);
        As[aCol + 0][aRow] = a4.x;
        As[aCol + 1][aRow] = a4.y;
        As[aCol + 2][aRow] = a4.z;
        As[aCol + 3][aRow] = a4.w;

        float4 b4 = *(const float4*)(B + (size_t)(k0 + bRow) * N + bx * BN + bCol);
        *(float4*)(&Bs[bRow][bCol]) = b4;

        __syncthreads();
#pragma unroll
        for (int k = 0; k < BK; k++) {
            float ar[TM], br[TN];
#pragma unroll
            for (int i = 0; i < TM; i++) ar[i] = As[k][ty * TM + i];
#pragma unroll
            for (int jj = 0; jj < TN; jj++) br[jj] = Bs[k][tx * TN + jj];
#pragma unroll
            for (int i = 0; i < TM; i++)
#pragma unroll
                for (int jj = 0; jj < TN; jj++)
                    acc[i][jj] += ar[i] * br[jj];
        }
        __syncthreads();
    }

#pragma unroll
    for (int i = 0; i < TM; i++) {
        int row = by * BM + ty * TM + i;
        if (row >= M) continue;
        float* crow = C + (size_t)row * N + cColBase;
#pragma unroll
        for (int jj = 0; jj < TN; jj += 4) {
            float4 v;
            float b0 = bias ? bias[cColBase + jj + 0] : 0.f;
            float b1 = bias ? bias[cColBase + jj + 1] : 0.f;
            float b2 = bias ? bias[cColBase + jj + 2] : 0.f;
            float b3 = bias ? bias[cColBase + jj + 3] : 0.f;
            v.x = acc[i][jj + 0] + b0;
            v.y = acc[i][jj + 1] + b1;
            v.z = acc[i][jj + 2] + b2;
            v.w = acc[i][jj + 3] + b3;
            if (doRelu) {
                v.x = fmaxf(v.x, 0.f); v.y = fmaxf(v.y, 0.f);
                v.z = fmaxf(v.z, 0.f); v.w = fmaxf(v.w, 0.f);
            }
            *(float4*)(crow + jj) = v;
        }
    }
}

// ---------------- entry point ----------------
extern "C" void kernel_launch(void* const* d_in, const int* in_sizes, int n_in,
                              void* d_out, int out_size) {
    const float* x  = (const float*)d_in[0];      // [50000, 256]
    const void*  ei = d_in[1];                    // [2, 800000] int32 OR int64
    const float* ea = (const float*)d_in[2];      // [800000]
    const float* W1 = (const float*)d_in[3];      // [256, 512]
    const float* b1 = (const float*)d_in[4];
    const float* W2 = (const float*)d_in[5];      // [512, 256]
    const float* b2 = (const float*)d_in[6];
    const float* W3 = (const float*)d_in[7];      // [256, 128]
    const float* b3 = (const float*)d_in[8];
    float*       out = (float*)d_out;             // [50000, 128]

    float *deg, *enorm, *bufA, *bufB;
    int *cnt, *cur, *rowptr, *esrc;
    cudaGetSymbolAddress((void**)&deg,    g_deg);
    cudaGetSymbolAddress((void**)&cnt,    g_cnt);
    cudaGetSymbolAddress((void**)&cur,    g_cur);
    cudaGetSymbolAddress((void**)&rowptr, g_rowptr);
    cudaGetSymbolAddress((void**)&esrc,   g_esrc);
    cudaGetSymbolAddress((void**)&enorm,  g_enorm);
    cudaGetSymbolAddress((void**)&bufA,   g_bufA);
    cudaGetSymbolAddress((void**)&bufB,   g_bufB);

    const int TB = 256;
    int nbN = (NN + TB - 1) / TB;
    int nbE = (NE + TB - 1) / TB;
    int mTiles = (NN + BM - 1) / BM;   // 391

    // --- detect edge_index dtype, then build normalized CSR (by dst) ---
    detect_dtype<<<64, 256>>>((const unsigned int*)ei);
    init_node<<<nbN, TB>>>(deg, cnt, cur);
    edge_deg_count<<<nbE, TB>>>(ei, ea, deg, cnt);
    make_dinv<<<nbN, TB>>>(deg);
    scan_rowptr<<<1, 1024>>>(cnt, rowptr);
    edge_fill<<<nbE, TB>>>(ei, ea, deg, rowptr, cur, esrc, enorm);

    // --- layer 1: a1 = agg(x) [256]; h1 = relu(a1 @ W1 + b1) [512] ---
    agg_csr<<<NN, 256>>>(x, bufB, rowptr, esrc, enorm, deg, nullptr, 256, 0);
    sgemm<<<dim3(512 / BN, mTiles), 256>>>(bufB, W1, b1, bufA, NN, 512, 256, 1);

    // --- layer 2: t2 = h1 @ W2 [256]; h2 = relu(agg(t2) + b2) ---
    sgemm<<<dim3(256 / BN, mTiles), 256>>>(bufA, W2, nullptr, bufB, NN, 256, 512, 0);
    agg_csr<<<NN, 256>>>(bufB, bufA, rowptr, esrc, enorm, deg, b2, 256, 1);

    // --- layer 3: t3 = h2 @ W3 [128]; out = agg(t3) + b3 ---
    sgemm<<<dim3(128 / BN, mTiles), 256>>>(bufA, W3, nullptr, bufB, NN, 128, 256, 0);
    agg_csr<<<NN, 128>>>(bufB, out, rowptr, esrc, enorm, deg, b3, 128, 0);
}

// round 6
// speedup vs baseline: 1.5653x; 1.5653x over previous
#include <cuda_runtime.h>
#include <cuda_bf16.h>
#include <cstddef>
#include <cstdint>

#define NN 50000
#define NE 800000

// ---------------- scratch (device globals; no allocation allowed) ----------
__device__ int   g_is64;
__device__ float g_deg[NN];
__device__ int   g_cnt[NN];
__device__ int   g_cur[NN];
__device__ int   g_rowptr[NN + 1];
__device__ int   g_esrc[NE];
__device__ float g_enorm[NE];
__device__ float g_bufA[(size_t)NN * 512];
__device__ float g_bufB[(size_t)NN * 256];
__device__ __nv_bfloat16 g_Ahi[(size_t)NN * 512];
__device__ __nv_bfloat16 g_Alo[(size_t)NN * 512];
__device__ __nv_bfloat16 g_Wthi[512 * 512];
__device__ __nv_bfloat16 g_Wtlo[512 * 512];

// ---------------- helpers ----------------
__device__ __forceinline__ uint32_t smem_u32(const void* p) {
    uint32_t a;
    asm("{ .reg .u64 t; cvta.to.shared.u64 t, %1; cvt.u32.u64 %0, t; }" : "=r"(a) : "l"(p));
    return a;
}
__device__ __forceinline__ void cp16(uint32_t dst, const void* src, int sz) {
    asm volatile("cp.async.cg.shared.global [%0], [%1], 16, %2;"
                 :: "r"(dst), "l"(src), "r"(sz) : "memory");
}
__device__ __forceinline__ void cp_commit() {
    asm volatile("cp.async.commit_group;" ::: "memory");
}
__device__ __forceinline__ void cp_wait1() {
    asm volatile("cp.async.wait_group 1;" ::: "memory");
}
__device__ __forceinline__ void cp_wait0() {
    asm volatile("cp.async.wait_group 0;" ::: "memory");
}
__device__ __forceinline__ void ldm_x4(uint32_t* r, uint32_t addr) {
    asm volatile("ldmatrix.sync.aligned.m8n8.x4.shared.b16 {%0,%1,%2,%3}, [%4];"
                 : "=r"(r[0]), "=r"(r[1]), "=r"(r[2]), "=r"(r[3]) : "r"(addr));
}
__device__ __forceinline__ void mma_bf16(float* c, const uint32_t* a, const uint32_t* b) {
    asm volatile(
        "mma.sync.aligned.m16n8k16.row.col.f32.bf16.bf16.f32 "
        "{%0,%1,%2,%3}, {%4,%5,%6,%7}, {%8,%9}, {%0,%1,%2,%3};"
        : "+f"(c[0]), "+f"(c[1]), "+f"(c[2]), "+f"(c[3])
        : "r"(a[0]), "r"(a[1]), "r"(a[2]), "r"(a[3]), "r"(b[0]), "r"(b[1]));
}

// ---------------- dtype detection ----------------
__global__ void detect_dtype(const unsigned int* __restrict__ w) {
    int tid = blockIdx.x * blockDim.x + threadIdx.x;
    for (int k = tid; k < NE; k += gridDim.x * blockDim.x) {
        if (w[2 * k + 1] != 0u) { g_is64 = 0; break; }
    }
}
__device__ __forceinline__ int load_idx(const void* ei, long long pos) {
    if (g_is64) return (int)((const long long*)ei)[pos];
    return ((const int*)ei)[pos];
}

// ---------------- preprocessing ----------------
__global__ void init_node(float* deg, int* cnt, int* cur) {
    int i = blockIdx.x * blockDim.x + threadIdx.x;
    if (i == 0) g_is64 = 1;
    if (i < NN) { deg[i] = 1.0f; cnt[i] = 0; cur[i] = 0; }
}
__global__ void edge_deg_count(const void* __restrict__ ei, const float* __restrict__ w,
                               float* deg, int* cnt) {
    int e = blockIdx.x * blockDim.x + threadIdx.x;
    if (e >= NE) return;
    int d = load_idx(ei, (long long)NE + e);
    if ((unsigned)d >= NN) return;
    atomicAdd(&deg[d], w[e]);
    atomicAdd(&cnt[d], 1);
}
__global__ void make_dinv(float* deg) {
    int i = blockIdx.x * blockDim.x + threadIdx.x;
    if (i < NN) deg[i] = rsqrtf(deg[i]);
}
__global__ void scan_rowptr(const int* __restrict__ cnt, int* __restrict__ rowptr) {
    __shared__ int sh[1024];
    const int n = NN;
    int t = threadIdx.x;
    int chunk = (n + 1023) >> 10;
    int b = t * chunk;
    int e = b + chunk; if (e > n) e = n;
    if (b > n) b = n;
    int sum = 0;
    for (int i = b; i < e; i++) sum += cnt[i];
    sh[t] = sum;
    __syncthreads();
    for (int off = 1; off < 1024; off <<= 1) {
        int v = (t >= off) ? sh[t - off] : 0;
        __syncthreads();
        sh[t] += v;
        __syncthreads();
    }
    int run = (t == 0) ? 0 : sh[t - 1];
    for (int i = b; i < e; i++) { rowptr[i] = run; run += cnt[i]; }
    if (t == 1023) rowptr[n] = sh[1023];
}
__global__ void edge_fill(const void* __restrict__ ei, const float* __restrict__ w,
                          const float* __restrict__ dinv, const int* __restrict__ rowptr,
                          int* cur, int* esrc, float* enorm) {
    int e = blockIdx.x * blockDim.x + threadIdx.x;
    if (e >= NE) return;
    int s = load_idx(ei, e);
    int d = load_idx(ei, (long long)NE + e);
    if ((unsigned)s >= NN || (unsigned)d >= NN) return;
    float nm = dinv[s] * w[e] * dinv[d];
    int pos = rowptr[d] + atomicAdd(&cur[d], 1);
    esrc[pos] = s;
    enorm[pos] = nm;
}

// ---------------- CSR gather-reduce aggregation ----------------
__global__ void agg_csr(const float* __restrict__ H, float* __restrict__ out,
                        const int* __restrict__ rowptr, const int* __restrict__ esrc,
                        const float* __restrict__ enorm, const float* __restrict__ dinv,
                        const float* __restrict__ bias, int D, int doRelu) {
    int i = blockIdx.x;
    int d = threadIdx.x;
    float di = dinv[i];
    float acc = di * di * H[(size_t)i * D + d];
    if (bias) acc += bias[d];
    int jb = rowptr[i], je = rowptr[i + 1];
    float acc2 = 0.f;
    int j = jb;
    for (; j + 1 < je; j += 2) {
        int s0 = esrc[j], s1 = esrc[j + 1];
        float n0 = enorm[j], n1 = enorm[j + 1];
        acc  += n0 * H[(size_t)s0 * D + d];
        acc2 += n1 * H[(size_t)s1 * D + d];
    }
    if (j < je) acc += enorm[j] * H[(size_t)esrc[j] * D + d];
    acc += acc2;
    if (doRelu) acc = fmaxf(acc, 0.f);
    out[(size_t)i * D + d] = acc;
}

// ---------------- split-precision conversion ----------------
__global__ void split_bf16(const float4* __restrict__ a, __nv_bfloat162* __restrict__ hi,
                           __nv_bfloat162* __restrict__ lo, int n4) {
    int i = blockIdx.x * blockDim.x + threadIdx.x;
    if (i >= n4) return;
    float4 v = a[i];
    __nv_bfloat16 h0 = __float2bfloat16_rn(v.x);
    __nv_bfloat16 h1 = __float2bfloat16_rn(v.y);
    __nv_bfloat16 h2 = __float2bfloat16_rn(v.z);
    __nv_bfloat16 h3 = __float2bfloat16_rn(v.w);
    __nv_bfloat16 l0 = __float2bfloat16_rn(v.x - __bfloat162float(h0));
    __nv_bfloat16 l1 = __float2bfloat16_rn(v.y - __bfloat162float(h1));
    __nv_bfloat16 l2 = __float2bfloat16_rn(v.z - __bfloat162float(h2));
    __nv_bfloat16 l3 = __float2bfloat16_rn(v.w - __bfloat162float(h3));
    hi[2 * i]     = __halves2bfloat162(h0, h1);
    hi[2 * i + 1] = __halves2bfloat162(h2, h3);
    lo[2 * i]     = __halves2bfloat162(l0, l1);
    lo[2 * i + 1] = __halves2bfloat162(l2, l3);
}

// Wt[n][k] = W[k][n], split into hi/lo
__global__ void wsplit(const float* __restrict__ W, __nv_bfloat16* __restrict__ th,
                       __nv_bfloat16* __restrict__ tl, int K, int N) {
    int i = blockIdx.x * blockDim.x + threadIdx.x;
    if (i >= K * N) return;
    int n = i / K, k = i - n * K;
    float x = W[(size_t)k * N + n];
    __nv_bfloat16 h = __float2bfloat16_rn(x);
    th[i] = h;
    tl[i] = __float2bfloat16_rn(x - __bfloat162float(h));
}

// ---------------- split-bf16 GEMM via mma.sync (HMMA) ----------------
// C[M,N] = A[M,K] @ W[K,N] (+bias, relu), A as hi/lo [M,K], W as hi/lo [N,K].
// Block tile 128x128, BK=32, 8 warps in 4(m) x 2(n), warp tile 32x64.
// smem per array tile: 128 rows x 40 halves (32 data + 8 pad) = 10240 B.
#define GLDA 40                      // padded halves per smem row
#define TILE_B 10240                 // one array tile bytes
#define STAGE_B (4 * TILE_B)         // Ah, Al, Bh, Bl
#define GEMM_SMEM (2 * STAGE_B)      // double buffered = 81920

__global__ __launch_bounds__(256)
void gemm_mma(const __nv_bfloat16* __restrict__ Ahi, const __nv_bfloat16* __restrict__ Alo,
              const __nv_bfloat16* __restrict__ Bhi, const __nv_bfloat16* __restrict__ Blo,
              const float* __restrict__ bias, float* __restrict__ C,
              int M, int N, int K, int doRelu)
{
    extern __shared__ __align__(16) char smem[];
    uint32_t sb = smem_u32(smem);
    int tid = threadIdx.x;
    int wid = tid >> 5;
    int lane = tid & 31;
    int wm = wid & 3;                // warp m index (0..3) -> rows wm*32
    int wn = wid >> 2;               // warp n index (0..1) -> cols wn*64
    int mbase = blockIdx.y * 128;
    int nbase = blockIdx.x * 128;

    float acc[2][8][4];
#pragma unroll
    for (int i = 0; i < 2; i++)
#pragma unroll
        for (int j = 0; j < 8; j++)
#pragma unroll
            for (int q = 0; q < 4; q++) acc[i][j][q] = 0.f;

    const __nv_bfloat16* srcs[4] = { Ahi, Alo, Bhi, Blo };
    int nchunk = K >> 5;

    // ---- stage loader: 4 arrays x 128 rows x 4 chunks(16B) = 2048 cp.async ----
    auto load_stage = [&](int s, int kb) {
#pragma unroll
        for (int it = 0; it < 8; ++it) {
            int i = tid + (it << 8);
            int arr = i >> 9;
            int rem = i & 511;
            int row = rem >> 2;
            int ck  = rem & 3;
            bool isA = arr < 2;
            int grow = (isA ? mbase : nbase) + row;
            int sz = 16;
            long long goff = 0;
            if (isA && grow >= M) sz = 0;
            else goff = (long long)grow * K + kb + ck * 8;
            uint32_t dst = sb + s * STAGE_B + arr * TILE_B + row * (GLDA * 2) + ck * 16;
            cp16(dst, srcs[arr] + goff, sz);
        }
        cp_commit();
    };

    load_stage(0, 0);
    if (nchunk > 1) load_stage(1, 32);

    for (int c = 0; c < nchunk; ++c) {
        if (c + 1 < nchunk) { cp_wait1(); } else { cp_wait0(); }
        __syncthreads();

        uint32_t stg = sb + (c & 1) * STAGE_B;
        uint32_t aBase = stg;                    // Ah
        uint32_t bBase = stg + 2 * TILE_B;       // Bh

#pragma unroll
        for (int ks = 0; ks < 2; ++ks) {
            // A fragments: addr row = wm*32 + mf*16 + quad pattern
            uint32_t ah[2][4], al[2][4];
#pragma unroll
            for (int mf = 0; mf < 2; ++mf) {
                int mrow = wm * 32 + mf * 16 + ((lane & 8) ? 8 : 0) + (lane & 7);
                int kcol = ks * 16 + ((lane >> 4) << 3);
                uint32_t off = (uint32_t)(mrow * GLDA + kcol) * 2;
                ldm_x4(ah[mf], aBase + off);
                ldm_x4(al[mf], aBase + TILE_B + off);
            }
            // B fragments: x4 packs two n-frags (n0-7 in r0r1, n8-15 in r2r3)
            uint32_t bh[8][2], bl[8][2];
#pragma unroll
            for (int p = 0; p < 4; ++p) {
                int q = lane >> 3;
                int nrow = wn * 64 + p * 16 + ((q >> 1) << 3) + (lane & 7);
                int kcol = ks * 16 + ((q & 1) << 3);
                uint32_t off = (uint32_t)(nrow * GLDA + kcol) * 2;
                uint32_t r4[4];
                ldm_x4(r4, bBase + off);
                bh[2 * p][0] = r4[0]; bh[2 * p][1] = r4[1];
                bh[2 * p + 1][0] = r4[2]; bh[2 * p + 1][1] = r4[3];
                ldm_x4(r4, bBase + TILE_B + off);
                bl[2 * p][0] = r4[0]; bl[2 * p][1] = r4[1];
                bl[2 * p + 1][0] = r4[2]; bl[2 * p + 1][1] = r4[3];
            }
            // 3-term split MMAs
#pragma unroll
            for (int mf = 0; mf < 2; ++mf)
#pragma unroll
                for (int nf = 0; nf < 8; ++nf) {
                    mma_bf16(acc[mf][nf], ah[mf], bh[nf]);
                    mma_bf16(acc[mf][nf], ah[mf], bl[nf]);
                    mma_bf16(acc[mf][nf], al[mf], bh[nf]);
                }
        }
        __syncthreads();
        if (c + 2 < nchunk) load_stage(c & 1, (c + 2) * 32);
    }

    // ---- epilogue ----
#pragma unroll
    for (int mf = 0; mf < 2; ++mf) {
        int row0 = mbase + wm * 32 + mf * 16 + (lane >> 2);
#pragma unroll
        for (int nf = 0; nf < 8; ++nf) {
            int col = nbase + wn * 64 + nf * 8 + ((lane & 3) << 1);
            float b0 = bias ? bias[col] : 0.f;
            float b1 = bias ? bias[col + 1] : 0.f;
            float2 v0 = { acc[mf][nf][0] + b0, acc[mf][nf][1] + b1 };
            float2 v1 = { acc[mf][nf][2] + b0, acc[mf][nf][3] + b1 };
            if (doRelu) {
                v0.x = fmaxf(v0.x, 0.f); v0.y = fmaxf(v0.y, 0.f);
                v1.x = fmaxf(v1.x, 0.f); v1.y = fmaxf(v1.y, 0.f);
            }
            if (row0 < M)     *(float2*)(C + (size_t)row0 * N + col) = v0;
            if (row0 + 8 < M) *(float2*)(C + (size_t)(row0 + 8) * N + col) = v1;
        }
    }
}

// ---------------- entry point ----------------
extern "C" void kernel_launch(void* const* d_in, const int* in_sizes, int n_in,
                              void* d_out, int out_size) {
    const float* x  = (const float*)d_in[0];
    const void*  ei = d_in[1];
    const float* ea = (const float*)d_in[2];
    const float* W1 = (const float*)d_in[3];
    const float* b1 = (const float*)d_in[4];
    const float* W2 = (const float*)d_in[5];
    const float* b2 = (const float*)d_in[6];
    const float* W3 = (const float*)d_in[7];
    const float* b3 = (const float*)d_in[8];
    float*       out = (float*)d_out;

    float *deg, *enorm, *bufA, *bufB;
    int *cnt, *cur, *rowptr, *esrc;
    __nv_bfloat16 *Ahi, *Alo, *Wth, *Wtl;
    cudaGetSymbolAddress((void**)&deg,    g_deg);
    cudaGetSymbolAddress((void**)&cnt,    g_cnt);
    cudaGetSymbolAddress((void**)&cur,    g_cur);
    cudaGetSymbolAddress((void**)&rowptr, g_rowptr);
    cudaGetSymbolAddress((void**)&esrc,   g_esrc);
    cudaGetSymbolAddress((void**)&enorm,  g_enorm);
    cudaGetSymbolAddress((void**)&bufA,   g_bufA);
    cudaGetSymbolAddress((void**)&bufB,   g_bufB);
    cudaGetSymbolAddress((void**)&Ahi,    g_Ahi);
    cudaGetSymbolAddress((void**)&Alo,    g_Alo);
    cudaGetSymbolAddress((void**)&Wth,    g_Wthi);
    cudaGetSymbolAddress((void**)&Wtl,    g_Wtlo);

    cudaFuncSetAttribute(gemm_mma, cudaFuncAttributeMaxDynamicSharedMemorySize, GEMM_SMEM);

    const int TB = 256;
    int nbN = (NN + TB - 1) / TB;
    int nbE = (NE + TB - 1) / TB;
    int mTiles = (NN + 127) / 128;   // 391

    // --- build normalized CSR (by dst) ---
    init_node<<<nbN, TB>>>(deg, cnt, cur);            // also sets g_is64 = 1
    detect_dtype<<<64, 256>>>((const unsigned int*)ei);
    edge_deg_count<<<nbE, TB>>>(ei, ea, deg, cnt);
    make_dinv<<<nbN, TB>>>(deg);
    scan_rowptr<<<1, 1024>>>(cnt, rowptr);
    edge_fill<<<nbE, TB>>>(ei, ea, deg, rowptr, cur, esrc, enorm);

    // --- layer 1: a1 = agg(x) [256]; h1 = relu(a1 @ W1 + b1) [512] ---
    agg_csr<<<NN, 256>>>(x, bufB, rowptr, esrc, enorm, deg, nullptr, 256, 0);
    {
        int n4 = NN * 256 / 4;
        split_bf16<<<(n4 + 255) / 256, 256>>>((const float4*)bufB,
                                              (__nv_bfloat162*)Ahi, (__nv_bfloat162*)Alo, n4);
        wsplit<<<(256 * 512 + 255) / 256, 256>>>(W1, Wth, Wtl, 256, 512);
        gemm_mma<<<dim3(4, mTiles), 256, GEMM_SMEM>>>(Ahi, Alo, Wth, Wtl, b1, bufA,
                                                      NN, 512, 256, 1);
    }

    // --- layer 2: t2 = h1 @ W2 [256]; h2 = relu(agg(t2) + b2) ---
    {
        int n4 = NN * 512 / 4;
        split_bf16<<<(n4 + 255) / 256, 256>>>((const float4*)bufA,
                                              (__nv_bfloat162*)Ahi, (__nv_bfloat162*)Alo, n4);
        wsplit<<<(512 * 256 + 255) / 256, 256>>>(W2, Wth, Wtl, 512, 256);
        gemm_mma<<<dim3(2, mTiles), 256, GEMM_SMEM>>>(Ahi, Alo, Wth, Wtl, nullptr, bufB,
                                                      NN, 256, 512, 0);
    }
    agg_csr<<<NN, 256>>>(bufB, bufA, rowptr, esrc, enorm, deg, b2, 256, 1);

    // --- layer 3: t3 = h2 @ W3 [128]; out = agg(t3) + b3 ---
    {
        int n4 = NN * 256 / 4;
        split_bf16<<<(n4 + 255) / 256, 256>>>((const float4*)bufA,
                                              (__nv_bfloat162*)Ahi, (__nv_bfloat162*)Alo, n4);
        wsplit<<<(256 * 128 + 255) / 256, 256>>>(W3, Wth, Wtl, 256, 128);
        gemm_mma<<<dim3(1, mTiles), 256, GEMM_SMEM>>>(Ahi, Alo, Wth, Wtl, nullptr, bufB,
                                                      NN, 128, 256, 0);
    }
    agg_csr<<<NN, 128>>>(bufB, out, rowptr, esrc, enorm, deg, b3, 128, 0);
}

// round 10
// speedup vs baseline: 1.6192x; 1.0344x over previous
#include <cuda_runtime.h>
#include <cuda_bf16.h>
#include <cstddef>
#include <cstdint>

#define NN 50000
#define NE 800000

// ---------------- scratch (device globals; no allocation allowed) ----------
__device__ int   g_is64;
__device__ float g_deg[NN];
__device__ int   g_cnt[NN];
__device__ int   g_cur[NN];
__device__ int   g_rowptr[NN + 1];
__device__ int   g_esrc[NE];
__device__ float g_enorm[NE];
__device__ float g_bufB[(size_t)NN * 256];           // t2 / t3 (fp32)
__device__ __nv_bfloat16 g_Phi[(size_t)NN * 512];    // hi pair P
__device__ __nv_bfloat16 g_Plo[(size_t)NN * 512];
__device__ __nv_bfloat16 g_Qhi[(size_t)NN * 512];    // hi pair Q
__device__ __nv_bfloat16 g_Qlo[(size_t)NN * 512];
__device__ __nv_bfloat16 g_Wthi[512 * 512];
__device__ __nv_bfloat16 g_Wtlo[512 * 512];

// ---------------- helpers ----------------
__device__ __forceinline__ uint32_t smem_u32(const void* p) {
    uint32_t a;
    asm("{ .reg .u64 t; cvta.to.shared.u64 t, %1; cvt.u32.u64 %0, t; }" : "=r"(a) : "l"(p));
    return a;
}
__device__ __forceinline__ void cp16(uint32_t dst, const void* src, int sz) {
    asm volatile("cp.async.cg.shared.global [%0], [%1], 16, %2;"
                 :: "r"(dst), "l"(src), "r"(sz) : "memory");
}
__device__ __forceinline__ void cp_commit() {
    asm volatile("cp.async.commit_group;" ::: "memory");
}
__device__ __forceinline__ void cp_wait1() {
    asm volatile("cp.async.wait_group 1;" ::: "memory");
}
__device__ __forceinline__ void cp_wait0() {
    asm volatile("cp.async.wait_group 0;" ::: "memory");
}
__device__ __forceinline__ void ldm_x4(uint32_t* r, uint32_t addr) {
    asm volatile("ldmatrix.sync.aligned.m8n8.x4.shared.b16 {%0,%1,%2,%3}, [%4];"
                 : "=r"(r[0]), "=r"(r[1]), "=r"(r[2]), "=r"(r[3]) : "r"(addr));
}
__device__ __forceinline__ void mma_bf16(float* c, const uint32_t* a, const uint32_t* b) {
    asm volatile(
        "mma.sync.aligned.m16n8k16.row.col.f32.bf16.bf16.f32 "
        "{%0,%1,%2,%3}, {%4,%5,%6,%7}, {%8,%9}, {%0,%1,%2,%3};"
        : "+f"(c[0]), "+f"(c[1]), "+f"(c[2]), "+f"(c[3])
        : "r"(a[0]), "r"(a[1]), "r"(a[2]), "r"(a[3]), "r"(b[0]), "r"(b[1]));
}
__device__ __forceinline__ __nv_bfloat162 split_pair(float x, float y,
                                                     __nv_bfloat162* lo) {
    __nv_bfloat16 hx = __float2bfloat16_rn(x);
    __nv_bfloat16 hy = __float2bfloat16_rn(y);
    *lo = __halves2bfloat162(__float2bfloat16_rn(x - __bfloat162float(hx)),
                             __float2bfloat16_rn(y - __bfloat162float(hy)));
    return __halves2bfloat162(hx, hy);
}

// ---------------- dtype detection ----------------
__global__ void detect_dtype(const unsigned int* __restrict__ w) {
    int tid = blockIdx.x * blockDim.x + threadIdx.x;
    for (int k = tid; k < NE; k += gridDim.x * blockDim.x) {
        if (w[2 * k + 1] != 0u) { g_is64 = 0; break; }
    }
}
__device__ __forceinline__ int load_idx(const void* ei, long long pos) {
    if (g_is64) return (int)((const long long*)ei)[pos];
    return ((const int*)ei)[pos];
}

// ---------------- preprocessing ----------------
__global__ void init_node(float* deg, int* cnt, int* cur) {
    int i = blockIdx.x * blockDim.x + threadIdx.x;
    if (i == 0) g_is64 = 1;
    if (i < NN) { deg[i] = 1.0f; cnt[i] = 0; cur[i] = 0; }
}
__global__ void edge_deg_count(const void* __restrict__ ei, const float* __restrict__ w,
                               float* deg, int* cnt) {
    int e = blockIdx.x * blockDim.x + threadIdx.x;
    if (e >= NE) return;
    int d = load_idx(ei, (long long)NE + e);
    if ((unsigned)d >= NN) return;
    atomicAdd(&deg[d], w[e]);
    atomicAdd(&cnt[d], 1);
}
__global__ void make_dinv(float* deg) {
    int i = blockIdx.x * blockDim.x + threadIdx.x;
    if (i < NN) deg[i] = rsqrtf(deg[i]);
}
__global__ void scan_rowptr(const int* __restrict__ cnt, int* __restrict__ rowptr) {
    __shared__ int sh[1024];
    const int n = NN;
    int t = threadIdx.x;
    int chunk = (n + 1023) >> 10;
    int b = t * chunk;
    int e = b + chunk; if (e > n) e = n;
    if (b > n) b = n;
    int sum = 0;
    for (int i = b; i < e; i++) sum += cnt[i];
    sh[t] = sum;
    __syncthreads();
    for (int off = 1; off < 1024; off <<= 1) {
        int v = (t >= off) ? sh[t - off] : 0;
        __syncthreads();
        sh[t] += v;
        __syncthreads();
    }
    int run = (t == 0) ? 0 : sh[t - 1];
    for (int i = b; i < e; i++) { rowptr[i] = run; run += cnt[i]; }
    if (t == 1023) rowptr[n] = sh[1023];
}
__global__ void edge_fill(const void* __restrict__ ei, const float* __restrict__ w,
                          const float* __restrict__ dinv, const int* __restrict__ rowptr,
                          int* cur, int* esrc, float* enorm) {
    int e = blockIdx.x * blockDim.x + threadIdx.x;
    if (e >= NE) return;
    int s = load_idx(ei, e);
    int d = load_idx(ei, (long long)NE + e);
    if ((unsigned)s >= NN || (unsigned)d >= NN) return;
    float nm = dinv[s] * w[e] * dinv[d];
    int pos = rowptr[d] + atomicAdd(&cur[d], 1);
    esrc[pos] = s;
    enorm[pos] = nm;
}

// ---------------- CSR gather-reduce aggregation ----------------
// Computes a[i,d] = (opt bias) + dinv^2 H[i,d] + sum norm_j H[src_j,d]; optional relu.
// outMode 0: write fp32 to outF. outMode 1: write split hi/lo bf16 to outH/outL.
__global__ void agg_csr(const float* __restrict__ H, float* __restrict__ outF,
                        __nv_bfloat16* __restrict__ outH, __nv_bfloat16* __restrict__ outL,
                        const int* __restrict__ rowptr, const int* __restrict__ esrc,
                        const float* __restrict__ enorm, const float* __restrict__ dinv,
                        const float* __restrict__ bias, int D, int doRelu, int outMode) {
    int i = blockIdx.x;
    int d = threadIdx.x;
    float di = dinv[i];
    float acc = di * di * H[(size_t)i * D + d];
    if (bias) acc += bias[d];
    int jb = rowptr[i], je = rowptr[i + 1];
    float acc2 = 0.f;
    int j = jb;
    for (; j + 1 < je; j += 2) {
        int s0 = esrc[j], s1 = esrc[j + 1];
        float n0 = enorm[j], n1 = enorm[j + 1];
        acc  += n0 * H[(size_t)s0 * D + d];
        acc2 += n1 * H[(size_t)s1 * D + d];
    }
    if (j < je) acc += enorm[j] * H[(size_t)esrc[j] * D + d];
    acc += acc2;
    if (doRelu) acc = fmaxf(acc, 0.f);
    if (outMode == 0) {
        outF[(size_t)i * D + d] = acc;
    } else {
        __nv_bfloat16 h = __float2bfloat16_rn(acc);
        outH[(size_t)i * D + d] = h;
        outL[(size_t)i * D + d] = __float2bfloat16_rn(acc - __bfloat162float(h));
    }
}

// Wt[n][k] = W[k][n], split into hi/lo
__global__ void wsplit(const float* __restrict__ W, __nv_bfloat16* __restrict__ th,
                       __nv_bfloat16* __restrict__ tl, int K, int N) {
    int i = blockIdx.x * blockDim.x + threadIdx.x;
    if (i >= K * N) return;
    int n = i / K, k = i - n * K;
    float x = W[(size_t)k * N + n];
    __nv_bfloat16 h = __float2bfloat16_rn(x);
    th[i] = h;
    tl[i] = __float2bfloat16_rn(x - __bfloat162float(h));
}

// ---------------- split-bf16 GEMM via mma.sync (HMMA) ----------------
// C[M,N] = A[M,K] @ W[K,N] (+bias, relu), A as hi/lo [M,K], W as hi/lo [N,K].
// Block tile 128x128, BK=32, 8 warps in 4(m) x 2(n), warp tile 32x64.
// outSplit=0: write fp32 C. outSplit=1: write hi/lo bf16 Chi/Clo.
#define GLDA 40                      // padded halves per smem row
#define TILE_B 10240                 // one array tile bytes
#define STAGE_B (4 * TILE_B)         // Ah, Al, Bh, Bl
#define GEMM_SMEM (2 * STAGE_B)      // double buffered = 81920

__global__ __launch_bounds__(256)
void gemm_mma(const __nv_bfloat16* __restrict__ Ahi, const __nv_bfloat16* __restrict__ Alo,
              const __nv_bfloat16* __restrict__ Bhi, const __nv_bfloat16* __restrict__ Blo,
              const float* __restrict__ bias, float* __restrict__ C,
              __nv_bfloat16* __restrict__ Chi, __nv_bfloat16* __restrict__ Clo,
              int M, int N, int K, int doRelu, int outSplit)
{
    extern __shared__ __align__(16) char smem[];
    uint32_t sb = smem_u32(smem);
    int tid = threadIdx.x;
    int wid = tid >> 5;
    int lane = tid & 31;
    int wm = wid & 3;                // warp m index (0..3) -> rows wm*32
    int wn = wid >> 2;               // warp n index (0..1) -> cols wn*64
    int mbase = blockIdx.y * 128;
    int nbase = blockIdx.x * 128;

    float acc[2][8][4];
#pragma unroll
    for (int i = 0; i < 2; i++)
#pragma unroll
        for (int j = 0; j < 8; j++)
#pragma unroll
            for (int q = 0; q < 4; q++) acc[i][j][q] = 0.f;

    const __nv_bfloat16* srcs[4] = { Ahi, Alo, Bhi, Blo };
    int nchunk = K >> 5;

    auto load_stage = [&](int s, int kb) {
#pragma unroll
        for (int it = 0; it < 8; ++it) {
            int i = tid + (it << 8);
            int arr = i >> 9;
            int rem = i & 511;
            int row = rem >> 2;
            int ck  = rem & 3;
            bool isA = arr < 2;
            int grow = (isA ? mbase : nbase) + row;
            int sz = 16;
            long long goff = 0;
            if (isA && grow >= M) sz = 0;
            else goff = (long long)grow * K + kb + ck * 8;
            uint32_t dst = sb + s * STAGE_B + arr * TILE_B + row * (GLDA * 2) + ck * 16;
            cp16(dst, srcs[arr] + goff, sz);
        }
        cp_commit();
    };

    load_stage(0, 0);
    if (nchunk > 1) load_stage(1, 32);

    for (int c = 0; c < nchunk; ++c) {
        if (c + 1 < nchunk) { cp_wait1(); } else { cp_wait0(); }
        __syncthreads();

        uint32_t stg = sb + (c & 1) * STAGE_B;
        uint32_t aBase = stg;
        uint32_t bBase = stg + 2 * TILE_B;

#pragma unroll
        for (int ks = 0; ks < 2; ++ks) {
            uint32_t ah[2][4], al[2][4];
#pragma unroll
            for (int mf = 0; mf < 2; ++mf) {
                int mrow = wm * 32 + mf * 16 + ((lane & 8) ? 8 : 0) + (lane & 7);
                int kcol = ks * 16 + ((lane >> 4) << 3);
                uint32_t off = (uint32_t)(mrow * GLDA + kcol) * 2;
                ldm_x4(ah[mf], aBase + off);
                ldm_x4(al[mf], aBase + TILE_B + off);
            }
            uint32_t bh[8][2], bl[8][2];
#pragma unroll
            for (int p = 0; p < 4; ++p) {
                int q = lane >> 3;
                int nrow = wn * 64 + p * 16 + ((q >> 1) << 3) + (lane & 7);
                int kcol = ks * 16 + ((q & 1) << 3);
                uint32_t off = (uint32_t)(nrow * GLDA + kcol) * 2;
                uint32_t r4[4];
                ldm_x4(r4, bBase + off);
                bh[2 * p][0] = r4[0]; bh[2 * p][1] = r4[1];
                bh[2 * p + 1][0] = r4[2]; bh[2 * p + 1][1] = r4[3];
                ldm_x4(r4, bBase + TILE_B + off);
                bl[2 * p][0] = r4[0]; bl[2 * p][1] = r4[1];
                bl[2 * p + 1][0] = r4[2]; bl[2 * p + 1][1] = r4[3];
            }
#pragma unroll
            for (int mf = 0; mf < 2; ++mf)
#pragma unroll
                for (int nf = 0; nf < 8; ++nf) {
                    mma_bf16(acc[mf][nf], ah[mf], bh[nf]);
                    mma_bf16(acc[mf][nf], ah[mf], bl[nf]);
                    mma_bf16(acc[mf][nf], al[mf], bh[nf]);
                }
        }
        __syncthreads();
        if (c + 2 < nchunk) load_stage(c & 1, (c + 2) * 32);
    }

    // ---- epilogue ----
#pragma unroll
    for (int mf = 0; mf < 2; ++mf) {
        int row0 = mbase + wm * 32 + mf * 16 + (lane >> 2);
#pragma unroll
        for (int nf = 0; nf < 8; ++nf) {
            int col = nbase + wn * 64 + nf * 8 + ((lane & 3) << 1);
            float b0 = bias ? bias[col] : 0.f;
            float b1 = bias ? bias[col + 1] : 0.f;
            float2 v0 = { acc[mf][nf][0] + b0, acc[mf][nf][1] + b1 };
            float2 v1 = { acc[mf][nf][2] + b0, acc[mf][nf][3] + b1 };
            if (doRelu) {
                v0.x = fmaxf(v0.x, 0.f); v0.y = fmaxf(v0.y, 0.f);
                v1.x = fmaxf(v1.x, 0.f); v1.y = fmaxf(v1.y, 0.f);
            }
            if (outSplit) {
                __nv_bfloat162 lo0, lo1;
                __nv_bfloat162 hi0 = split_pair(v0.x, v0.y, &lo0);
                __nv_bfloat162 hi1 = split_pair(v1.x, v1.y, &lo1);
                if (row0 < M) {
                    *(__nv_bfloat162*)(Chi + (size_t)row0 * N + col) = hi0;
                    *(__nv_bfloat162*)(Clo + (size_t)row0 * N + col) = lo0;
                }
                if (row0 + 8 < M) {
                    *(__nv_bfloat162*)(Chi + (size_t)(row0 + 8) * N + col) = hi1;
                    *(__nv_bfloat162*)(Clo + (size_t)(row0 + 8) * N + col) = lo1;
                }
            } else {
                if (row0 < M)     *(float2*)(C + (size_t)row0 * N + col) = v0;
                if (row0 + 8 < M) *(float2*)(C + (size_t)(row0 + 8) * N + col) = v1;
            }
        }
    }
}

// ---------------- entry point ----------------
extern "C" void kernel_launch(void* const* d_in, const int* in_sizes, int n_in,
                              void* d_out, int out_size) {
    const float* x  = (const float*)d_in[0];
    const void*  ei = d_in[1];
    const float* ea = (const float*)d_in[2];
    const float* W1 = (const float*)d_in[3];
    const float* b1 = (const float*)d_in[4];
    const float* W2 = (const float*)d_in[5];
    const float* b2 = (const float*)d_in[6];
    const float* W3 = (const float*)d_in[7];
    const float* b3 = (const float*)d_in[8];
    float*       out = (float*)d_out;

    float *deg, *enorm, *bufB;
    int *cnt, *cur, *rowptr, *esrc;
    __nv_bfloat16 *Phi, *Plo, *Qhi, *Qlo, *Wth, *Wtl;
    cudaGetSymbolAddress((void**)&deg,    g_deg);
    cudaGetSymbolAddress((void**)&cnt,    g_cnt);
    cudaGetSymbolAddress((void**)&cur,    g_cur);
    cudaGetSymbolAddress((void**)&rowptr, g_rowptr);
    cudaGetSymbolAddress((void**)&esrc,   g_esrc);
    cudaGetSymbolAddress((void**)&enorm,  g_enorm);
    cudaGetSymbolAddress((void**)&bufB,   g_bufB);
    cudaGetSymbolAddress((void**)&Phi,    g_Phi);
    cudaGetSymbolAddress((void**)&Plo,    g_Plo);
    cudaGetSymbolAddress((void**)&Qhi,    g_Qhi);
    cudaGetSymbolAddress((void**)&Qlo,    g_Qlo);
    cudaGetSymbolAddress((void**)&Wth,    g_Wthi);
    cudaGetSymbolAddress((void**)&Wtl,    g_Wtlo);

    cudaFuncSetAttribute(gemm_mma, cudaFuncAttributeMaxDynamicSharedMemorySize, GEMM_SMEM);

    const int TB = 256;
    int nbN = (NN + TB - 1) / TB;
    int nbE = (NE + TB - 1) / TB;
    int mTiles = (NN + 127) / 128;   // 391

    // --- build normalized CSR (by dst) ---
    init_node<<<nbN, TB>>>(deg, cnt, cur);            // also sets g_is64 = 1
    detect_dtype<<<64, 256>>>((const unsigned int*)ei);
    edge_deg_count<<<nbE, TB>>>(ei, ea, deg, cnt);
    make_dinv<<<nbN, TB>>>(deg);
    scan_rowptr<<<1, 1024>>>(cnt, rowptr);
    edge_fill<<<nbE, TB>>>(ei, ea, deg, rowptr, cur, esrc, enorm);

    // --- layer 1: P = split(agg(x)) [256]; Q = split(relu(P @ W1 + b1)) [512] ---
    agg_csr<<<NN, 256>>>(x, nullptr, Phi, Plo, rowptr, esrc, enorm, deg,
                         nullptr, 256, 0, 1);
    wsplit<<<(256 * 512 + 255) / 256, 256>>>(W1, Wth, Wtl, 256, 512);
    gemm_mma<<<dim3(4, mTiles), 256, GEMM_SMEM>>>(Phi, Plo, Wth, Wtl, b1,
                                                  nullptr, Qhi, Qlo,
                                                  NN, 512, 256, 1, 1);

    // --- layer 2: t2 = Q @ W2 [256] (fp32); P = split(relu(agg(t2) + b2)) ---
    wsplit<<<(512 * 256 + 255) / 256, 256>>>(W2, Wth, Wtl, 512, 256);
    gemm_mma<<<dim3(2, mTiles), 256, GEMM_SMEM>>>(Qhi, Qlo, Wth, Wtl, nullptr,
                                                  bufB, nullptr, nullptr,
                                                  NN, 256, 512, 0, 0);
    agg_csr<<<NN, 256>>>(bufB, nullptr, Phi, Plo, rowptr, esrc, enorm, deg,
                         b2, 256, 1, 1);

    // --- layer 3: t3 = P @ W3 [128] (fp32); out = agg(t3) + b3 ---
    wsplit<<<(256 * 128 + 255) / 256, 256>>>(W3, Wth, Wtl, 256, 128);
    gemm_mma<<<dim3(1, mTiles), 256, GEMM_SMEM>>>(Phi, Plo, Wth, Wtl, nullptr,
                                                  bufB, nullptr, nullptr,
                                                  NN, 128, 256, 0, 0);
    agg_csr<<<NN, 128>>>(bufB, out, nullptr, nullptr, rowptr, esrc, enorm, deg,
                         b3, 128, 0, 0);
}